// round 2
// baseline (speedup 1.0000x reference)
#include <cuda_runtime.h>

// Problem dims
#define NN    128            // H == W == kernel_size
#define NH    65             // half-spectrum width (N/2+1)
#define NHP   68             // padded row stride for Yc (32B-aligned w' chunks)
#define NB    32             // batch
#define NC    64             // in channels
#define NO    64             // out channels
#define NBC   (NB*NC)        // 2048
#define NBO   (NB*NO)        // 2048
#define NFREQ (NH*NN)        // 8320, f = wp*128 + h
#define LDF   129            // smem FFT row stride (bank-conflict mitigation)

// ---------------- scratch (device globals; allocation-free rule) ----------------
__device__ float2 g_X1[(size_t)NBC * NH * NN];     // [b*c][wp][h]   136 MB
__device__ float2 g_Xf[(size_t)NFREQ * NB * NC];   // [f][b][c]      136 MB
__device__ float2 g_Wf[(size_t)NFREQ * NC * NO];   // [f][c][o]      273 MB
__device__ float2 g_Yf[(size_t)NFREQ * NB * NO];   // [f][b][o]      136 MB
__device__ float2 g_Yc[(size_t)NBO * NN * NHP];    // [bo][h][wp]    143 MB

// ---------------- packed f32x2 helpers (FFMA2) ----------------
__device__ __forceinline__ unsigned long long pk2(float x, float y) {
    unsigned long long r;
    asm("mov.b64 %0, {%1, %2};" : "=l"(r) : "f"(x), "f"(y));
    return r;
}
__device__ __forceinline__ void ffma2(unsigned long long& d, unsigned long long a, unsigned long long b) {
    asm("fma.rn.f32x2 %0, %1, %2, %0;" : "+l"(d) : "l"(a), "l"(b));
}
__device__ __forceinline__ float2 unpk2(unsigned long long v) {
    float2 f;
    asm("mov.b64 {%0, %1}, %2;" : "=f"(f.x), "=f"(f.y) : "l"(v));
    return f;
}

// ---------------- shared-memory Stockham radix-2 FFT, length 128 ----------------
// tw[k] = exp(-2*pi*i*k/128), k in [0,64)
__device__ __forceinline__ void init_tw(float2* tw) {
    int tid = threadIdx.x;
    if (tid < 64) {
        float s, c;
        sincospif(-(float)tid * (1.0f / 64.0f), &s, &c);
        tw[tid] = make_float2(c, s);
    }
}

// 16 FFTs of length 128 per block (256 threads). DIF Stockham, autosorted.
// Input in bufA (row stride LDF), result lands in bufB. SIGN=-1 fwd, +1 inv.
template <int SIGN>
__device__ __forceinline__ void fft128_block16(float2* bufA, float2* bufB, const float2* tw) {
    int tid = threadIdx.x;
    float2* src = bufA;
    float2* dst = bufB;
#pragma unroll
    for (int st = 0; st < 7; st++) {
        const int s = 1 << st;
#pragma unroll
        for (int itb = 0; itb < 4; itb++) {            // 16*64 / 256 = 4
            int it  = tid + itb * 256;
            int fi  = it >> 6;
            int idx = it & 63;
            float2* S = src + fi * LDF;
            float2* D = dst + fi * LDF;
            float2 a = S[idx];
            float2 b = S[idx + 64];
            int tk = idx & ~(s - 1);
            float2 w = tw[tk];
            float wy = (SIGN < 0) ? w.y : -w.y;
            float2 sum = make_float2(a.x + b.x, a.y + b.y);
            float2 dif = make_float2(a.x - b.x, a.y - b.y);
            float2 t = make_float2(dif.x * w.x - dif.y * wy,
                                   dif.x * wy + dif.y * w.x);
            int lo = idx + tk;
            D[lo]     = sum;
            D[lo + s] = t;
        }
        __syncthreads();
        float2* tmp = src; src = dst; dst = tmp;
    }
    // 7 swaps (odd): result is in bufB
}

// ---------------- K1: forward row FFT (real x -> half spectrum), transpose to [bc][wp][h]
__global__ void __launch_bounds__(256) k1_rowfft(const float* __restrict__ x) {
    __shared__ float2 bufA[16 * LDF], bufB[16 * LDF];
    __shared__ float2 tw[64];
    init_tw(tw);
    int tid = threadIdx.x;
    int blk = blockIdx.x;
    int bc = blk >> 3;
    int h0 = (blk & 7) << 4;
    const float* xp = x + (size_t)bc * NN * NN + (size_t)h0 * NN;
    for (int i = tid; i < 16 * NN; i += 256) {
        int r = i >> 7, w = i & 127;
        bufA[r * LDF + w] = make_float2(xp[i], 0.f);
    }
    __syncthreads();
    fft128_block16<-1>(bufA, bufB, tw);
    float2* out = g_X1 + (size_t)bc * NH * NN;
    for (int i = tid; i < NH * 16; i += 256) {
        int wp = i >> 4, r = i & 15;
        out[(size_t)wp * NN + h0 + r] = bufB[r * LDF + wp];
    }
}

// ---------------- K2: forward column FFT, scatter to freq-major [f][b][c]
__global__ void __launch_bounds__(256) k2_colfft() {
    __shared__ float2 bufA[16 * LDF], bufB[16 * LDF];
    __shared__ float2 tw[64];
    init_tw(tw);
    int tid = threadIdx.x;
    int blk = blockIdx.x;                 // b*260 + wp*4 + ct
    int b   = blk / (NH * 4);
    int rem = blk % (NH * 4);
    int wp  = rem >> 2;
    int c0  = (rem & 3) << 4;
    for (int i = tid; i < 16 * NN; i += 256) {
        int h = i & 127, cl = i >> 7;
        bufA[cl * LDF + h] =
            g_X1[((size_t)(b * NC + c0 + cl) * NH + wp) * NN + h];
    }
    __syncthreads();
    fft128_block16<-1>(bufA, bufB, tw);
    for (int i = tid; i < 16 * NN; i += 256) {
        int cl = i & 15, h = i >> 4;
        g_Xf[((size_t)(wp * NN + h)) * NBC + b * NC + c0 + cl] = bufB[cl * LDF + h];
    }
}

// ---------------- KW: build Hermitianized weights Weff[f][c][o] = 0.5*(W[k] + conj(W[-k]))
__global__ void __launch_bounds__(256) kw_weff(const float* __restrict__ wr,
                                               const float* __restrict__ wi) {
    __shared__ float2 S[64][17];          // [o][wl], padded
    int tid = threadIdx.x;
    int blk = blockIdx.x;                 // c*(128*5) + h*5 + wt
    int c   = blk / (NN * 5);
    int rem = blk % (NN * 5);
    int h   = rem / 5;
    int wt  = rem % 5;
    int wp0 = wt << 4;
    int h2  = (NN - h) & 127;
    for (int i = tid; i < 1024; i += 256) {
        int wl = i & 15, o = i >> 4;
        int wp = wp0 + wl;                // < 80 < 128: in-bounds read even past NH
        int w2 = (NN - wp) & 127;
        size_t base = (size_t)(o * NC + c) * (NN * NN);
        float a1 = wr[base + (size_t)h  * NN + wp];
        float b1 = wi[base + (size_t)h  * NN + wp];
        float a2 = wr[base + (size_t)h2 * NN + w2];
        float b2 = wi[base + (size_t)h2 * NN + w2];
        S[o][wl] = make_float2(0.5f * (a1 + a2), 0.5f * (b1 - b2));
    }
    __syncthreads();
    for (int i = tid; i < 1024; i += 256) {
        int o = i & 63, wl = i >> 6;
        int wp = wp0 + wl;
        if (wp < NH)
            g_Wf[((size_t)(wp * NN + h)) * (NC * NO) + c * NO + o] = S[o][wl];
    }
}

// ---------------- K3: per-frequency complex GEMM  Y[b][o] = sum_c X[b][c] * Weff[c][o]
__global__ void __launch_bounds__(256) k3_contract() {
    __shared__ float Xr_s[NC][NB];        // 8 KB
    __shared__ float Xi_s[NC][NB];        // 8 KB
    __shared__ float Wr[NC][NO];          // 16 KB
    __shared__ float Wi[NC][NO];          // 16 KB  (total 48 KB)
    int tid = threadIdx.x;
    int f = blockIdx.x;
    const float2* __restrict__ Xg = g_Xf + (size_t)f * (NB * NC);
    const float2* __restrict__ Wg = g_Wf + (size_t)f * (NC * NO);
    for (int i = tid; i < NB * NC; i += 256) {
        float2 v = Xg[i];
        int b = i >> 6, c = i & 63;
        Xr_s[c][b] = v.x;
        Xi_s[c][b] = v.y;
    }
    for (int i = tid; i < NC * NO; i += 256) {
        float2 v = Wg[i];
        int c = i >> 6, o = i & 63;
        Wr[c][o] = v.x;
        Wi[c][o] = v.y;
    }
    __syncthreads();

    int b  = tid & 31;
    int o0 = (tid >> 5) << 3;             // 8 outputs per thread (4 o-pairs)
    unsigned long long ar[4], ai[4];
#pragma unroll
    for (int k = 0; k < 4; k++) { ar[k] = 0ull; ai[k] = 0ull; }

#pragma unroll 4
    for (int c = 0; c < NC; c++) {
        float xr = Xr_s[c][b];
        float xi = Xi_s[c][b];
        unsigned long long xr2 = pk2(xr, xr);
        unsigned long long xi2 = pk2(xi, xi);
        unsigned long long xn2 = pk2(-xi, -xi);
        const unsigned long long* wr2 = (const unsigned long long*)&Wr[c][o0];
        const unsigned long long* wi2 = (const unsigned long long*)&Wi[c][o0];
#pragma unroll
        for (int k = 0; k < 4; k++) {
            unsigned long long wrv = wr2[k];
            unsigned long long wiv = wi2[k];
            ffma2(ar[k], xr2, wrv);       // ar += xr*wr
            ffma2(ar[k], xn2, wiv);       // ar -= xi*wi
            ffma2(ai[k], xr2, wiv);       // ai += xr*wi
            ffma2(ai[k], xi2, wrv);       // ai += xi*wr
        }
    }
    float2* Yg = g_Yf + (size_t)f * (NB * NO);
#pragma unroll
    for (int k = 0; k < 4; k++) {
        float2 arv = unpk2(ar[k]);
        float2 aiv = unpk2(ai[k]);
        float4 o2 = make_float4(arv.x, aiv.x, arv.y, aiv.y);
        *(float4*)&Yg[b * NO + o0 + 2 * k] = o2;   // 16B-aligned
    }
}

// ---------------- K4: inverse column FFT (along h), to [bo][h][wp] (padded)
__global__ void __launch_bounds__(256) k4_colifft() {
    __shared__ float2 bufA[16 * LDF], bufB[16 * LDF];
    __shared__ float2 tw[64];
    init_tw(tw);
    int tid = threadIdx.x;
    int blk = blockIdx.x;                 // bt*17 + wt
    int bt = blk / 17;
    int wt = blk % 17;
    int bo0 = bt << 2;
    int wp0 = wt << 2;
    for (int i = tid; i < 16 * NN; i += 256) {
        int bl = i & 3, wl = (i >> 2) & 3, h = i >> 4;
        int wp = wp0 + wl;
        int fi = (wl << 2) + bl;
        float2 v = make_float2(0.f, 0.f);
        if (wp < NH)
            v = g_Yf[((size_t)(wp * NN + h)) * NBO + bo0 + bl];
        bufA[fi * LDF + h] = v;
    }
    __syncthreads();
    fft128_block16<1>(bufA, bufB, tw);
    for (int i = tid; i < 16 * NN; i += 256) {
        int wl = i & 3, bl = (i >> 2) & 3, h = i >> 4;
        int wp = wp0 + wl;
        int fi = (wl << 2) + bl;
        if (wp < NH)
            g_Yc[((size_t)(bo0 + bl) * NN + h) * NHP + wp] = bufB[fi * LDF + h];
    }
}

// ---------------- K5: inverse row FFT (Hermitian mirror), scale + bias + relu
__global__ void __launch_bounds__(256) k5_rowifft(const float* __restrict__ bias,
                                                  float* __restrict__ out) {
    __shared__ float2 bufA[16 * LDF], bufB[16 * LDF];
    __shared__ float2 tw[64];
    init_tw(tw);
    int tid = threadIdx.x;
    int blk = blockIdx.x;                 // bo*8 + ht
    int bo = blk >> 3;
    int h0 = (blk & 7) << 4;
    int o  = bo & 63;
    const float2* Yrow = g_Yc + (size_t)bo * NN * NHP;
    for (int i = tid; i < 16 * NN; i += 256) {
        int r = i >> 7, w = i & 127;
        int wp = (w <= 64) ? w : (NN - w);
        float2 v = Yrow[(size_t)(h0 + r) * NHP + wp];
        if (w > 64) v.y = -v.y;           // conj mirror (row is Hermitian in w)
        bufA[r * LDF + w] = v;
    }
    __syncthreads();
    fft128_block16<1>(bufA, bufB, tw);
    float bv = bias[o];
    const float scale = 1.0f / 16384.0f;  // 1/N^2 (ifftn normalization)
    float* op = out + (size_t)bo * NN * NN + (size_t)h0 * NN;
    for (int i = tid; i < 16 * NN; i += 256) {
        int r = i >> 7, w = i & 127;
        float val = bufB[r * LDF + w].x * scale + bv;
        op[(size_t)r * NN + w] = fmaxf(val, 0.f);
    }
}

// ---------------- launch ----------------
extern "C" void kernel_launch(void* const* d_in, const int* in_sizes, int n_in,
                              void* d_out, int out_size) {
    const float* x    = (const float*)d_in[0];
    const float* wr   = (const float*)d_in[1];
    const float* wi   = (const float*)d_in[2];
    const float* bias = (const float*)d_in[3];
    float* out = (float*)d_out;

    k1_rowfft <<<NBC * 8, 256>>>(x);            // 16384 blocks
    kw_weff   <<<NC * NN * 5, 256>>>(wr, wi);   // 40960 blocks
    k2_colfft <<<NB * NH * 4, 256>>>();         // 8320 blocks
    k3_contract<<<NFREQ, 256>>>();              // 8320 blocks
    k4_colifft<<<(NBO / 4) * 17, 256>>>();      // 8704 blocks
    k5_rowifft<<<NBO * 8, 256>>>(bias, out);    // 16384 blocks
}

// round 3
// speedup vs baseline: 1.1949x; 1.1949x over previous
#include <cuda_runtime.h>

// Problem dims
#define NN    128            // H == W == kernel_size
#define NH    65             // half-spectrum width (N/2+1)
#define NHP   68             // padded row stride for Yc
#define NB    32             // batch
#define NC    64             // in channels
#define NO    64             // out channels
#define NBC   (NB*NC)        // 2048
#define NBO   (NB*NO)        // 2048
#define NFREQ (NH*NN)        // 8320, f = wp*128 + h
#define LDF   129            // smem FFT row stride

// ---------------- scratch (device globals; allocation-free rule) ----------------
__device__ float2 g_X1[(size_t)NBC * NH * NN];     // [b*c][wp][h]
__device__ float2 g_Xf[(size_t)NFREQ * NB * NC];   // [f][b][c]
__device__ float2 g_Wf[(size_t)NFREQ * NC * NO];   // [f][c][o]
__device__ float2 g_Yf[(size_t)NFREQ * NB * NO];   // [f][b][o]
__device__ float2 g_Yc[(size_t)NBO * NN * NHP];    // [bo][h][wp]

// ---------------- packed f32x2 helpers (FFMA2) ----------------
__device__ __forceinline__ unsigned long long pk2(float x, float y) {
    unsigned long long r;
    asm("mov.b64 %0, {%1, %2};" : "=l"(r) : "f"(x), "f"(y));
    return r;
}
__device__ __forceinline__ void ffma2(unsigned long long& d, unsigned long long a, unsigned long long b) {
    asm("fma.rn.f32x2 %0, %1, %2, %0;" : "+l"(d) : "l"(a), "l"(b));
}
__device__ __forceinline__ float2 unpk2(unsigned long long v) {
    float2 f;
    asm("mov.b64 {%0, %1}, %2;" : "=f"(f.x), "=f"(f.y) : "l"(v));
    return f;
}

// ---------------- FFT helpers ----------------
__device__ __forceinline__ void init_tw(float2* tw) {
    int tid = threadIdx.x;
    if (tid < 64) {
        float s, c;
        sincospif(-(float)tid * (1.0f / 64.0f), &s, &c);
        tw[tid] = make_float2(c, s);
    }
}

__device__ __forceinline__ float2 f2add(float2 a, float2 b) { return make_float2(a.x + b.x, a.y + b.y); }
__device__ __forceinline__ float2 f2sub(float2 a, float2 b) { return make_float2(a.x - b.x, a.y - b.y); }

template <int SIGN>
__device__ __forceinline__ float2 cmul_tw(float2 w, float2 z) {
    float wy = (SIGN < 0) ? w.y : -w.y;
    return make_float2(z.x * w.x - z.y * wy, z.x * wy + z.y * w.x);
}

// XOR swizzle used on the group1->group2 intermediate buffer only
#define SWZI(p) ((p) ^ ((((unsigned)(p)) >> 4) & 7))

// Fused 3x radix-2 (= radix-8) Stockham group. 16 threads per FFT, each
// handling 8 points. S = base stride of the first of the three fused stages
// (S=1 covers strides 1,2,4; S=8 covers 8,16,32). Exact recomposition of the
// radix-2 Stockham stages: stage outputs land at Q + k*S, Q = i + 7*tk.
template <int SIGN, int S, bool SWZ_ST, bool SWZ_LD>
__device__ __forceinline__ void radix8_group(const float2* src, float2* dst, const float2* tw) {
    int tid = threadIdx.x;
    int fi = tid >> 4;
    int i  = tid & 15;
    const int tk = i & ~(S - 1);
    const float2* Sr = src + fi * LDF;
    float2* Dr = dst + fi * LDF;

    float2 a[8];
#pragma unroll
    for (int k = 0; k < 8; k++) {
        int p = i + 16 * k;
        if (SWZ_LD) p = SWZI(p);
        a[k] = Sr[p];
    }
    // stage A (stride S): butterflies (a[k], a[k+4]) with tw[tk+16k]
    float2 v[4], u[4];
#pragma unroll
    for (int k = 0; k < 4; k++) {
        v[k] = f2add(a[k], a[k + 4]);
        u[k] = cmul_tw<SIGN>(tw[tk + 16 * k], f2sub(a[k], a[k + 4]));
    }
    // stage B (stride 2S): pairs (v0,v2),(u0,u2) w/ tw[2tk]; (v1,v3),(u1,u3) w/ tw[2tk+32]
    float2 w0 = tw[2 * tk], w1 = tw[2 * tk + 32];
    float2 g[4], h[4];
    g[0] = f2add(v[0], v[2]);  g[2] = cmul_tw<SIGN>(w0, f2sub(v[0], v[2]));
    g[1] = f2add(u[0], u[2]);  g[3] = cmul_tw<SIGN>(w0, f2sub(u[0], u[2]));
    h[0] = f2add(v[1], v[3]);  h[2] = cmul_tw<SIGN>(w1, f2sub(v[1], v[3]));
    h[1] = f2add(u[1], u[3]);  h[3] = cmul_tw<SIGN>(w1, f2sub(u[1], u[3]));
    // stage C (stride 4S): pairs (g[k], h[k]) with tw[4tk]
    float2 w2 = tw[4 * tk];
    float2 e[8];
#pragma unroll
    for (int k = 0; k < 4; k++) {
        e[k]     = f2add(g[k], h[k]);
        e[k + 4] = cmul_tw<SIGN>(w2, f2sub(g[k], h[k]));
    }
    const int Q = i + 7 * tk;
#pragma unroll
    for (int k = 0; k < 8; k++) {
        int p = Q + k * S;
        if (SWZ_ST) p = SWZI(p);
        Dr[p] = e[k];
    }
}

// 16 FFTs of length 128 per block (256 threads). Input bufA, result bufB.
template <int SIGN>
__device__ __forceinline__ void fft128_block16(float2* bufA, float2* bufB, const float2* tw) {
    radix8_group<SIGN, 1, true,  false>(bufA, bufB, tw);   // strides 1,2,4
    __syncthreads();
    radix8_group<SIGN, 8, false, true >(bufB, bufA, tw);   // strides 8,16,32
    __syncthreads();
    // final radix-2, stride 64 (twiddle = 1)
    int tid = threadIdx.x;
#pragma unroll
    for (int itb = 0; itb < 4; itb++) {
        int it  = tid + itb * 256;
        int f2  = it >> 6;
        int idx = it & 63;
        float2 x = bufA[f2 * LDF + idx];
        float2 y = bufA[f2 * LDF + idx + 64];
        bufB[f2 * LDF + idx]      = f2add(x, y);
        bufB[f2 * LDF + idx + 64] = f2sub(x, y);
    }
    __syncthreads();
}

// ---------------- K1: forward row FFT (real x -> half spectrum), transpose to [bc][wp][h]
__global__ void __launch_bounds__(256) k1_rowfft(const float* __restrict__ x) {
    __shared__ float2 bufA[16 * LDF], bufB[16 * LDF];
    __shared__ float2 tw[64];
    init_tw(tw);
    int tid = threadIdx.x;
    int blk = blockIdx.x;
    int bc = blk >> 3;
    int h0 = (blk & 7) << 4;
    const float* xp = x + (size_t)bc * NN * NN + (size_t)h0 * NN;
    for (int i = tid; i < 16 * NN; i += 256) {
        int r = i >> 7, w = i & 127;
        bufA[r * LDF + w] = make_float2(xp[i], 0.f);
    }
    __syncthreads();
    fft128_block16<-1>(bufA, bufB, tw);
    float2* out = g_X1 + (size_t)bc * NH * NN;
    for (int i = tid; i < NH * 16; i += 256) {
        int wp = i >> 4, r = i & 15;
        out[(size_t)wp * NN + h0 + r] = bufB[r * LDF + wp];
    }
}

// ---------------- K2: forward column FFT, scatter to freq-major [f][b][c]
__global__ void __launch_bounds__(256) k2_colfft() {
    __shared__ float2 bufA[16 * LDF], bufB[16 * LDF];
    __shared__ float2 tw[64];
    init_tw(tw);
    int tid = threadIdx.x;
    int blk = blockIdx.x;                 // b*260 + wp*4 + ct
    int b   = blk / (NH * 4);
    int rem = blk % (NH * 4);
    int wp  = rem >> 2;
    int c0  = (rem & 3) << 4;
    for (int i = tid; i < 16 * NN; i += 256) {
        int h = i & 127, cl = i >> 7;
        bufA[cl * LDF + h] =
            g_X1[((size_t)(b * NC + c0 + cl) * NH + wp) * NN + h];
    }
    __syncthreads();
    fft128_block16<-1>(bufA, bufB, tw);
    for (int i = tid; i < 16 * NN; i += 256) {
        int cl = i & 15, h = i >> 4;
        g_Xf[((size_t)(wp * NN + h)) * NBC + b * NC + c0 + cl] = bufB[cl * LDF + h];
    }
}

// ---------------- KW: Weff[f][c][o] = 0.5*(W[k] + conj(W[-k]))
__global__ void __launch_bounds__(256) kw_weff(const float* __restrict__ wr,
                                               const float* __restrict__ wi) {
    __shared__ float2 S[64][17];
    int tid = threadIdx.x;
    int blk = blockIdx.x;                 // c*(128*5) + h*5 + wt
    int c   = blk / (NN * 5);
    int rem = blk % (NN * 5);
    int h   = rem / 5;
    int wt  = rem % 5;
    int wp0 = wt << 4;
    int h2  = (NN - h) & 127;
    for (int i = tid; i < 1024; i += 256) {
        int wl = i & 15, o = i >> 4;
        int wp = wp0 + wl;
        int w2 = (NN - wp) & 127;
        size_t base = (size_t)(o * NC + c) * (NN * NN);
        float a1 = wr[base + (size_t)h  * NN + wp];
        float b1 = wi[base + (size_t)h  * NN + wp];
        float a2 = wr[base + (size_t)h2 * NN + w2];
        float b2 = wi[base + (size_t)h2 * NN + w2];
        S[o][wl] = make_float2(0.5f * (a1 + a2), 0.5f * (b1 - b2));
    }
    __syncthreads();
    for (int i = tid; i < 1024; i += 256) {
        int o = i & 63, wl = i >> 6;
        int wp = wp0 + wl;
        if (wp < NH)
            g_Wf[((size_t)(wp * NN + h)) * (NC * NO) + c * NO + o] = S[o][wl];
    }
}

// ---------------- K3: per-frequency complex GEMM  Y[b][o] = sum_c X[b][c] * Weff[c][o]
// Register-blocked: each thread computes 2 batches x 4 outputs.
__global__ void __launch_bounds__(256) k3_contract() {
    __shared__ __align__(16) float Xr_s[NC][NB + 2];   // +2 pad: fill conflicts 32-way -> 2-way
    __shared__ __align__(16) float Xi_s[NC][NB + 2];
    __shared__ __align__(16) float Wr[NC][NO];
    __shared__ __align__(16) float Wi[NC][NO];
    int tid = threadIdx.x;
    int f = blockIdx.x;
    const float2* __restrict__ Xg = g_Xf + (size_t)f * (NB * NC);
    const float2* __restrict__ Wg = g_Wf + (size_t)f * (NC * NO);
    for (int i = tid; i < NB * NC; i += 256) {
        float2 v = Xg[i];
        int b = i >> 6, c = i & 63;
        Xr_s[c][b] = v.x;
        Xi_s[c][b] = v.y;
    }
    for (int i = tid; i < NC * NO; i += 256) {
        float2 v = Wg[i];
        int c = i >> 6, o = i & 63;
        Wr[c][o] = v.x;
        Wi[c][o] = v.y;
    }
    __syncthreads();

    int b0 = (tid & 15) << 1;             // 2 batches per thread
    int o0 = (tid >> 4) << 2;             // 4 outputs per thread (2 o-pairs)
    unsigned long long ar[2][2], ai[2][2];
#pragma unroll
    for (int bb = 0; bb < 2; bb++)
#pragma unroll
        for (int op = 0; op < 2; op++) { ar[bb][op] = 0ull; ai[bb][op] = 0ull; }

#pragma unroll 4
    for (int c = 0; c < NC; c++) {
        float2 xr = *(const float2*)&Xr_s[c][b0];
        float2 xi = *(const float2*)&Xi_s[c][b0];
        float4 wrv = *(const float4*)&Wr[c][o0];
        float4 wiv = *(const float4*)&Wi[c][o0];
        unsigned long long wr01 = pk2(wrv.x, wrv.y);
        unsigned long long wr23 = pk2(wrv.z, wrv.w);
        unsigned long long wi01 = pk2(wiv.x, wiv.y);
        unsigned long long wi23 = pk2(wiv.z, wiv.w);
#pragma unroll
        for (int bb = 0; bb < 2; bb++) {
            float xrb = bb ? xr.y : xr.x;
            float xib = bb ? xi.y : xi.x;
            unsigned long long xr2 = pk2(xrb, xrb);
            unsigned long long xi2 = pk2(xib, xib);
            unsigned long long xn2 = pk2(-xib, -xib);
            ffma2(ar[bb][0], xr2, wr01);
            ffma2(ar[bb][0], xn2, wi01);
            ffma2(ai[bb][0], xr2, wi01);
            ffma2(ai[bb][0], xi2, wr01);
            ffma2(ar[bb][1], xr2, wr23);
            ffma2(ar[bb][1], xn2, wi23);
            ffma2(ai[bb][1], xr2, wi23);
            ffma2(ai[bb][1], xi2, wr23);
        }
    }
    float2* Yg = g_Yf + (size_t)f * (NB * NO);
#pragma unroll
    for (int bb = 0; bb < 2; bb++)
#pragma unroll
        for (int op = 0; op < 2; op++) {
            float2 arv = unpk2(ar[bb][op]);
            float2 aiv = unpk2(ai[bb][op]);
            float4 o2 = make_float4(arv.x, aiv.x, arv.y, aiv.y);
            *(float4*)&Yg[(b0 + bb) * NO + o0 + 2 * op] = o2;   // 16B-aligned
        }
}

// ---------------- K4: inverse column FFT (along h), to [bo][h][wp] (padded)
__global__ void __launch_bounds__(256) k4_colifft() {
    __shared__ float2 bufA[16 * LDF], bufB[16 * LDF];
    __shared__ float2 tw[64];
    init_tw(tw);
    int tid = threadIdx.x;
    int blk = blockIdx.x;                 // bt*17 + wt
    int bt = blk / 17;
    int wt = blk % 17;
    int bo0 = bt << 2;
    int wp0 = wt << 2;
    for (int i = tid; i < 16 * NN; i += 256) {
        int bl = i & 3, wl = (i >> 2) & 3, h = i >> 4;
        int wp = wp0 + wl;
        int fi = (wl << 2) + bl;
        float2 v = make_float2(0.f, 0.f);
        if (wp < NH)
            v = g_Yf[((size_t)(wp * NN + h)) * NBO + bo0 + bl];
        bufA[fi * LDF + h] = v;
    }
    __syncthreads();
    fft128_block16<1>(bufA, bufB, tw);
    for (int i = tid; i < 16 * NN; i += 256) {
        int wl = i & 3, bl = (i >> 2) & 3, h = i >> 4;
        int wp = wp0 + wl;
        int fi = (wl << 2) + bl;
        if (wp < NH)
            g_Yc[((size_t)(bo0 + bl) * NN + h) * NHP + wp] = bufB[fi * LDF + h];
    }
}

// ---------------- K5: inverse row FFT (Hermitian mirror), scale + bias + relu
__global__ void __launch_bounds__(256) k5_rowifft(const float* __restrict__ bias,
                                                  float* __restrict__ out) {
    __shared__ float2 bufA[16 * LDF], bufB[16 * LDF];
    __shared__ float2 tw[64];
    init_tw(tw);
    int tid = threadIdx.x;
    int blk = blockIdx.x;                 // bo*8 + ht
    int bo = blk >> 3;
    int h0 = (blk & 7) << 4;
    int o  = bo & 63;
    const float2* Yrow = g_Yc + (size_t)bo * NN * NHP;
    for (int i = tid; i < 16 * NN; i += 256) {
        int r = i >> 7, w = i & 127;
        int wp = (w <= 64) ? w : (NN - w);
        float2 v = Yrow[(size_t)(h0 + r) * NHP + wp];
        if (w > 64) v.y = -v.y;           // conj mirror
        bufA[r * LDF + w] = v;
    }
    __syncthreads();
    fft128_block16<1>(bufA, bufB, tw);
    float bv = bias[o];
    const float scale = 1.0f / 16384.0f;  // 1/N^2 (ifftn normalization)
    float* op = out + (size_t)bo * NN * NN + (size_t)h0 * NN;
    for (int i = tid; i < 16 * NN; i += 256) {
        int r = i >> 7, w = i & 127;
        float val = bufB[r * LDF + w].x * scale + bv;
        op[(size_t)r * NN + w] = fmaxf(val, 0.f);
    }
}

// ---------------- launch ----------------
extern "C" void kernel_launch(void* const* d_in, const int* in_sizes, int n_in,
                              void* d_out, int out_size) {
    const float* x    = (const float*)d_in[0];
    const float* wr   = (const float*)d_in[1];
    const float* wi   = (const float*)d_in[2];
    const float* bias = (const float*)d_in[3];
    float* out = (float*)d_out;

    k1_rowfft <<<NBC * 8, 256>>>(x);            // 16384 blocks
    kw_weff   <<<NC * NN * 5, 256>>>(wr, wi);   // 40960 blocks
    k2_colfft <<<NB * NH * 4, 256>>>();         // 8320 blocks
    k3_contract<<<NFREQ, 256>>>();              // 8320 blocks
    k4_colifft<<<(NBO / 4) * 17, 256>>>();      // 8704 blocks
    k5_rowifft<<<NBO * 8, 256>>>(bias, out);    // 16384 blocks
}